// round 2
// baseline (speedup 1.0000x reference)
#include <cuda_runtime.h>

#define NPTS 2048
#define KCAP 256
#define NTHREADS 256
#define CUT2 0.09f

// d_out layout (float32 per harness __output__ dtype):
//   [0, N*K)            neighbours (N,K)
//   [N*K, N*K*4)        cell_indices (N,K,3)
//   [N*K*4]             actual_max
#define MAX_OFFSET ((size_t)NPTS * KCAP * 4)

__global__ void pb_init_kernel(float* __restrict__ out_max) {
    *out_max = 0.0f;   // bit pattern 0 => valid init for positive-float atomicMax-as-int
}

__global__ __launch_bounds__(NTHREADS)
void pb_nbr_kernel(const float* __restrict__ pos, float* __restrict__ out) {
    __shared__ float4 spos[NPTS];       // 32 KB
    __shared__ int warpcnt[NTHREADS / 32];
    __shared__ int s_count;

    const int tid  = threadIdx.x;
    const int i    = blockIdx.x;
    const int lane = tid & 31;
    const int w    = tid >> 5;
    const unsigned lmask = (1u << lane) - 1u;

    // Cooperative load of all positions into shared (padded float4 for LDS.128)
    for (int j = tid; j < NPTS; j += NTHREADS) {
        spos[j] = make_float4(pos[3 * j], pos[3 * j + 1], pos[3 * j + 2], 0.0f);
    }
    if (tid == 0) s_count = 0;
    __syncthreads();

    const float pix = spos[i].x;
    const float piy = spos[i].y;
    const float piz = spos[i].z;

    // Per-dimension shift feasibility (conservative margin 1e-4 >> fp32 rounding).
    // shift -1 along d needs p_j >= p_i + 0.7 (p_j < 1)  => feasible only if p_i < 0.3
    // shift +1 along d needs p_j <= p_i - 0.7 (p_j >= 0) => feasible only if p_i > 0.7
    const bool okx[3] = { pix < 0.30001f, true, pix > 0.69999f };
    const bool oky[3] = { piy < 0.30001f, true, piy > 0.69999f };
    const bool okz[3] = { piz < 0.30001f, true, piz > 0.69999f };

    float* __restrict__ out_neigh = out + (size_t)i * KCAP;
    float* __restrict__ out_cells = out + (size_t)NPTS * KCAP + (size_t)i * KCAP * 3;

    for (int c = 0; c < 27; c++) {
        const int sx = (c % 3) - 1;
        const int sy = ((c / 3) % 3) - 1;
        const int sz = (c / 9) - 1;
        if (!(okx[sx + 1] && oky[sy + 1] && okz[sz + 1])) continue;

        const float fsx = (float)sx, fsy = (float)sy, fsz = (float)sz;
        const bool selfc = (c == 13);

        for (int chunk = 0; chunk < NPTS; chunk += NTHREADS) {
            const int j = chunk + tid;
            const float4 p = spos[j];
            // Match reference rounding exactly: neigh = shift + p_j; delta = neigh - p_i;
            // d2 = dx*dx + dy*dy + dz*dz with plain (non-FMA) mul/add.
            const float dx = __fadd_rn(__fadd_rn(p.x, fsx), -pix);
            const float dy = __fadd_rn(__fadd_rn(p.y, fsy), -piy);
            const float dz = __fadd_rn(__fadd_rn(p.z, fsz), -piz);
            const float d2 = __fadd_rn(__fadd_rn(__fmul_rn(dx, dx), __fmul_rn(dy, dy)),
                                       __fmul_rn(dz, dz));
            const bool hit = (d2 <= CUT2) && !(selfc && (j == i));

            const unsigned b = __ballot_sync(0xFFFFFFFFu, hit);
            if (lane == 0) warpcnt[w] = __popc(b);
            __syncthreads();

            int pre = 0, tot = 0;
#pragma unroll
            for (int w2 = 0; w2 < NTHREADS / 32; w2++) {
                const int cnt = warpcnt[w2];
                pre += (w2 < w) ? cnt : 0;
                tot += cnt;
            }
            const int base = s_count;
            if (hit) {
                const int off = base + pre + __popc(b & lmask);
                if (off < KCAP) {
                    out_neigh[off]         = (float)j;
                    out_cells[3 * off]     = fsx;
                    out_cells[3 * off + 1] = fsy;
                    out_cells[3 * off + 2] = fsz;
                }
            }
            __syncthreads();
            if (tid == 0) s_count = base + tot;   // keep counting past KCAP for actual_max
        }
    }
    __syncthreads();

    const int total  = s_count;
    const int filled = total < KCAP ? total : KCAP;
    // Tail fill: neighbours = -1; cell_indices = (1,1,1) (jnp.take wraps -1 -> last row)
    for (int k = filled + tid; k < KCAP; k += NTHREADS) {
        out_neigh[k]         = -1.0f;
        out_cells[3 * k]     = 1.0f;
        out_cells[3 * k + 1] = 1.0f;
        out_cells[3 * k + 2] = 1.0f;
    }
    // actual_max: positive floats compare identically to their int bit patterns
    if (tid == 0) atomicMax((int*)(out + MAX_OFFSET), __float_as_int((float)total));
}

extern "C" void kernel_launch(void* const* d_in, const int* in_sizes, int n_in,
                              void* d_out, int out_size) {
    const float* pos = (const float*)d_in[0];
    float* out = (float*)d_out;
    pb_init_kernel<<<1, 1>>>(out + MAX_OFFSET);
    pb_nbr_kernel<<<NPTS, NTHREADS>>>(pos, out);
}

// round 4
// speedup vs baseline: 1.2735x; 1.2735x over previous
#include <cuda_runtime.h>

#define NPTS 2048
#define KCAP 256
#define NTHREADS 256
#define WARPS_PER_BLOCK (NTHREADS / 32)
#define CUT2 0.09f

// d_out layout (float32):
//   [0, N*K)            neighbours (N,K)
//   [N*K, N*K*4)        cell_indices (N,K,3)
//   [N*K*4]             actual_max
#define MAX_OFFSET ((size_t)NPTS * KCAP * 4)

__global__ void pb_init_kernel(float* __restrict__ out_max) {
    *out_max = 0.0f;
}

__global__ __launch_bounds__(NTHREADS)
void pb_nbr_kernel(const float* __restrict__ pos, float* __restrict__ out) {
    __shared__ float4 spos[NPTS];       // 32 KB, shared by 8 rows

    const int tid  = threadIdx.x;
    const int lane = tid & 31;
    const int w    = tid >> 5;
    const unsigned lmask = (1u << lane) - 1u;

    // Cooperative fill of the position cache (float4-padded for LDS.128)
    for (int j = tid; j < NPTS; j += NTHREADS) {
        spos[j] = make_float4(pos[3 * j], pos[3 * j + 1], pos[3 * j + 2], 0.0f);
    }
    __syncthreads();
    // After this point each warp is fully independent: no barriers, no shared state.

    const int i = blockIdx.x * WARPS_PER_BLOCK + w;   // row owned by this warp
    const float pix = spos[i].x;
    const float piy = spos[i].y;
    const float piz = spos[i].z;

    // Per-dimension shift feasibility (margin 1e-4 >> fp32 rounding).
    const bool okx[3] = { pix < 0.30001f, true, pix > 0.69999f };
    const bool oky[3] = { piy < 0.30001f, true, piy > 0.69999f };
    const bool okz[3] = { piz < 0.30001f, true, piz > 0.69999f };

    float* __restrict__ out_neigh = out + (size_t)i * KCAP;
    float* __restrict__ out_cells = out + (size_t)NPTS * KCAP + (size_t)i * KCAP * 3;

    int cnt = 0;   // uniform across the warp (updated from ballots only)

    for (int c = 0; c < 27; c++) {
        const int sx = (c % 3) - 1;
        const int sy = ((c / 3) % 3) - 1;
        const int sz = (c / 9) - 1;
        if (!(okx[sx + 1] && oky[sy + 1] && okz[sz + 1])) continue;

        const float fsx = (float)sx, fsy = (float)sy, fsz = (float)sz;
        const bool selfc = (c == 13);

        for (int chunk = 0; chunk < NPTS; chunk += 32) {
            const int j = chunk + lane;
            const float4 p = spos[j];
            // Exact reference rounding: ((p_j + s) - p_i), plain mul/add, no FMA.
            const float dx = __fadd_rn(__fadd_rn(p.x, fsx), -pix);
            const float dy = __fadd_rn(__fadd_rn(p.y, fsy), -piy);
            const float dz = __fadd_rn(__fadd_rn(p.z, fsz), -piz);
            const float d2 = __fadd_rn(__fadd_rn(__fmul_rn(dx, dx), __fmul_rn(dy, dy)),
                                       __fmul_rn(dz, dz));
            const bool hit = (d2 <= CUT2) && !(selfc && (j == i));

            const unsigned b = __ballot_sync(0xFFFFFFFFu, hit);
            if (b) {
                if (hit) {
                    const int off = cnt + __popc(b & lmask);
                    if (off < KCAP) {
                        out_neigh[off]         = (float)j;
                        out_cells[3 * off]     = fsx;
                        out_cells[3 * off + 1] = fsy;
                        out_cells[3 * off + 2] = fsz;
                    }
                }
                cnt += __popc(b);   // keep counting past KCAP for actual_max
            }
        }
    }

    const int filled = cnt < KCAP ? cnt : KCAP;
    // Tail fill: neighbours = -1; cell_indices = (1,1,1) (jnp.take wraps -1 -> last row)
    for (int k = filled + lane; k < KCAP; k += 32) {
        out_neigh[k]         = -1.0f;
        out_cells[3 * k]     = 1.0f;
        out_cells[3 * k + 1] = 1.0f;
        out_cells[3 * k + 2] = 1.0f;
    }
    // actual_max via monotone int-bits of positive floats
    if (lane == 0) atomicMax((int*)(out + MAX_OFFSET), __float_as_int((float)cnt));
}

extern "C" void kernel_launch(void* const* d_in, const int* in_sizes, int n_in,
                              void* d_out, int out_size) {
    const float* pos = (const float*)d_in[0];
    float* out = (float*)d_out;
    pb_init_kernel<<<1, 1>>>(out + MAX_OFFSET);
    pb_nbr_kernel<<<NPTS / WARPS_PER_BLOCK, NTHREADS>>>(pos, out);
}

// round 5
// speedup vs baseline: 1.6299x; 1.2799x over previous
#include <cuda_runtime.h>

#define NPTS 2048
#define KCAP 256
#define NTHREADS 256
#define ROWS_PER_BLOCK 2
#define WARPS_PER_ROW 4
#define STAGE_CAP 384
#define CUT2 0.09f

// d_out layout (float32):
//   [0, N*K)            neighbours (N,K)
//   [N*K, N*K*4)        cell_indices (N,K,3)
//   [N*K*4]             actual_max
#define MAX_OFFSET ((size_t)NPTS * KCAP * 4)

__global__ void pb_init_kernel(float* __restrict__ out_max) {
    *out_max = 0.0f;
}

__global__ __launch_bounds__(NTHREADS)
void pb_nbr_kernel(const float* __restrict__ pos, float* __restrict__ out) {
    __shared__ float4 spos[NPTS];                                    // 32 KB
    __shared__ int stage[ROWS_PER_BLOCK][WARPS_PER_ROW][STAGE_CAP];  // 12 KB
    __shared__ int scount[ROWS_PER_BLOCK][WARPS_PER_ROW];

    const int tid  = threadIdx.x;
    const int lane = tid & 31;
    const int w    = tid >> 5;
    const int r    = w >> 2;   // row within block (0..1)
    const int q    = w & 3;    // quarter of that row's work (0..3)
    const unsigned lmask = (1u << lane) - 1u;

    for (int j = tid; j < NPTS; j += NTHREADS) {
        spos[j] = make_float4(pos[3 * j], pos[3 * j + 1], pos[3 * j + 2], 0.0f);
    }
    __syncthreads();

    const int i = blockIdx.x * ROWS_PER_BLOCK + r;
    const float pix = spos[i].x;
    const float piy = spos[i].y;
    const float piz = spos[i].z;

    // Per-dimension shift feasibility (margin 1e-4 >> fp32 rounding).
    const bool okx[3] = { pix < 0.30001f, true, pix > 0.69999f };
    const bool oky[3] = { piy < 0.30001f, true, piy > 0.69999f };
    const bool okz[3] = { piz < 0.30001f, true, piz > 0.69999f };

    // Count active cells -> total ordered chunk count T = nA*64, quarter = nA*16.
    int nA = 0;
#pragma unroll
    for (int c = 0; c < 27; c++) {
        const int sx = (c % 3) - 1, sy = ((c / 3) % 3) - 1, sz = (c / 9) - 1;
        if (okx[sx + 1] && oky[sy + 1] && okz[sz + 1]) nA++;
    }
    const int per = nA * 16;          // chunks per quarter (T/4, exact)
    const int t0 = q * per;
    const int t1 = t0 + per;

    int* __restrict__ mystage = stage[r][q];
    int scnt = 0;                      // uniform in warp
    int tbase = 0;

    for (int c = 0; c < 27; c++) {
        const int sx = (c % 3) - 1, sy = ((c / 3) % 3) - 1, sz = (c / 9) - 1;
        if (!(okx[sx + 1] && oky[sy + 1] && okz[sz + 1])) continue;

        const int lo = (t0 > tbase) ? t0 : tbase;
        const int hi = (t1 < tbase + 64) ? t1 : tbase + 64;
        if (lo < hi) {
            const float fsx = (float)sx, fsy = (float)sy, fsz = (float)sz;
            const bool selfc = (c == 13);
            for (int t = lo; t < hi; t++) {
                const int j = ((t - tbase) << 5) + lane;
                const float4 p = spos[j];
                // Exact reference rounding: ((p_j + s) - p_i), plain mul/add, no FMA.
                const float dx = __fadd_rn(__fadd_rn(p.x, fsx), -pix);
                const float dy = __fadd_rn(__fadd_rn(p.y, fsy), -piy);
                const float dz = __fadd_rn(__fadd_rn(p.z, fsz), -piz);
                const float d2 = __fadd_rn(__fadd_rn(__fmul_rn(dx, dx), __fmul_rn(dy, dy)),
                                           __fmul_rn(dz, dz));
                const bool hit = (d2 <= CUT2) && !(selfc && (j == i));

                const unsigned b = __ballot_sync(0xFFFFFFFFu, hit);
                if (b) {
                    if (hit) {
                        const int idx = scnt + __popc(b & lmask);
                        if (idx < STAGE_CAP) mystage[idx] = (c << 11) | j;
                    }
                    scnt += __popc(b);
                }
            }
        }
        tbase += 64;
    }

    if (lane == 0) scount[r][q] = scnt;
    __syncthreads();

    int base = 0, rowTotal = 0;
#pragma unroll
    for (int q2 = 0; q2 < WARPS_PER_ROW; q2++) {
        const int cc = scount[r][q2];
        if (q2 < q) base += cc;
        rowTotal += cc;
    }

    float* __restrict__ out_neigh = out + (size_t)i * KCAP;
    float* __restrict__ out_cells = out + (size_t)NPTS * KCAP + (size_t)i * KCAP * 3;

    // Copy this warp's in-order staged segment to its prefix position.
    const int nwrite = (scnt < STAGE_CAP) ? scnt : STAGE_CAP;
    for (int e = lane; e < nwrite; e += 32) {
        const int off = base + e;
        if (off < KCAP) {
            const int code = mystage[e];
            const int j = code & 2047;
            const int c = code >> 11;
            out_neigh[off]         = (float)j;
            out_cells[3 * off]     = (float)((c % 3) - 1);
            out_cells[3 * off + 1] = (float)(((c / 3) % 3) - 1);
            out_cells[3 * off + 2] = (float)((c / 9) - 1);
        }
    }

    // Tail fill by the row's 128 threads: neighbours=-1, cells=(1,1,1)
    const int rowTid = tid & 127;
    const int filled = (rowTotal < KCAP) ? rowTotal : KCAP;
    for (int k = filled + rowTid; k < KCAP; k += 128) {
        out_neigh[k]         = -1.0f;
        out_cells[3 * k]     = 1.0f;
        out_cells[3 * k + 1] = 1.0f;
        out_cells[3 * k + 2] = 1.0f;
    }
    if (q == 0 && lane == 0) {
        atomicMax((int*)(out + MAX_OFFSET), __float_as_int((float)rowTotal));
    }
}

extern "C" void kernel_launch(void* const* d_in, const int* in_sizes, int n_in,
                              void* d_out, int out_size) {
    const float* pos = (const float*)d_in[0];
    float* out = (float*)d_out;
    pb_init_kernel<<<1, 1>>>(out + MAX_OFFSET);
    pb_nbr_kernel<<<NPTS / ROWS_PER_BLOCK, NTHREADS>>>(pos, out);
}